// round 5
// baseline (speedup 1.0000x reference)
#include <cuda_runtime.h>
#include <cuda_fp16.h>
#include <cstdint>

#define THREADS 512
#define TILE_M  64
#define FDIM    256
#define N_ITER  25

#define ROW_BYTES  512                         // 256 halfs per row
#define W_BYTES    (FDIM * ROW_BYTES)          // 131072
#define Z_BYTES    (TILE_M * ROW_BYTES)        // 32768 per buffer
#define SMEM_BYTES (W_BYTES + 2 * Z_BYTES)     // 196608 (192 KB)

static __device__ __forceinline__ uint32_t smem_u32(const void* p) {
    uint32_t a;
    asm("{ .reg .u64 t; cvta.to.shared.u64 t, %1; cvt.u32.u64 %0, t; }" : "=r"(a) : "l"(p));
    return a;
}

// Byte offset of half element (r, k) in a swizzled [rows x 256] fp16 tile.
// 16B units within each 512B row are XORed with (r & 7): conflict-free
// ldmatrix and STS across 8-row groups.
static __device__ __forceinline__ uint32_t swz(uint32_t r, uint32_t k) {
    return r * ROW_BYTES + (((k >> 3) ^ (r & 7)) << 4) + ((k & 7) << 1);
}

static __device__ __forceinline__ void ldsm4(uint32_t r[4], uint32_t addr) {
    asm volatile("ldmatrix.sync.aligned.m8n8.x4.shared.b16 {%0,%1,%2,%3}, [%4];"
                 : "=r"(r[0]), "=r"(r[1]), "=r"(r[2]), "=r"(r[3]) : "r"(addr));
}

static __device__ __forceinline__ void mma16816(float d[4], const uint32_t a[4],
                                                uint32_t b0, uint32_t b1) {
    asm volatile("mma.sync.aligned.m16n8k16.row.col.f32.f16.f16.f32 "
                 "{%0,%1,%2,%3}, {%4,%5,%6,%7}, {%8,%9}, {%0,%1,%2,%3};"
                 : "+f"(d[0]), "+f"(d[1]), "+f"(d[2]), "+f"(d[3])
                 : "r"(a[0]), "r"(a[1]), "r"(a[2]), "r"(a[3]), "r"(b0), "r"(b1));
}

// 1-MUFU fast tanh for interior iterations (error attenuated by contraction).
static __device__ __forceinline__ float tanh_fast(float x) {
    float y;
    asm("tanh.approx.f32 %0, %1;" : "=f"(y) : "f"(x));
    return y;
}

// Accurate tanh for the final iteration: 1 - 2/(1 + e^{2x}), ~1e-6 rel error.
static __device__ __forceinline__ float tanh_acc(float x) {
    float e, r;
    asm("ex2.approx.f32 %0, %1;" : "=f"(e) : "f"(x * 2.8853900817779268f)); // 2*log2(e)
    asm("rcp.approx.f32 %0, %1;" : "=f"(r) : "f"(1.0f + e));
    return 1.0f - 2.0f * r;
}

__global__ void __launch_bounds__(THREADS, 1)
fixed_point_kernel(const float* __restrict__ x, const float* __restrict__ W,
                   const float* __restrict__ b, float* __restrict__ out)
{
    extern __shared__ char smem[];
    const uint32_t sb  = smem_u32(smem);
    const uint32_t Wb  = sb;                 // W tile
    const uint32_t Zb0 = sb + W_BYTES;       // z ping
    const uint32_t Zb1 = Zb0 + Z_BYTES;      // z pong

    const int tid = threadIdx.x;
    const int wid = tid >> 5;
    const int l   = tid & 31;
    const int wm  = (wid & 1) << 5;          // 32-row half of the 64-row tile
    const int wn  = (wid >> 1) << 5;         // 32-col slice of the 256 cols
    const int row0 = blockIdx.x * TILE_M;

    // ---- Load W -> SMEM fp16, swizzled [n][k] (K-contiguous rows) ----
    for (int idx = tid; idx < FDIM * (FDIM / 4); idx += THREADS) {
        int n  = idx >> 6;
        int k4 = (idx & 63) << 2;
        float4 wv = *reinterpret_cast<const float4*>(W + n * FDIM + k4);
        __half2 h0 = __floats2half2_rn(wv.x, wv.y);
        __half2 h1 = __floats2half2_rn(wv.z, wv.w);
        uint2 v;
        v.x = *reinterpret_cast<uint32_t*>(&h0);
        v.y = *reinterpret_cast<uint32_t*>(&h1);
        *reinterpret_cast<uint2*>(smem + swz(n, k4)) = v;
    }

    // ---- c = x + b, register-resident fp32 in D-fragment layout (32 floats) ----
    const int qr = l >> 2;          // row within 8-row group
    const int qc = (l & 3) << 1;    // col pair within 8-col frag
    float c_frag[2][4][4];          // [m-frag][n-frag][quad]
#pragma unroll
    for (int mf = 0; mf < 2; ++mf)
#pragma unroll
        for (int half = 0; half < 2; ++half) {
            int r = row0 + wm + mf * 16 + qr + half * 8;
            const float* xr = x + (size_t)r * FDIM;
#pragma unroll
            for (int nf = 0; nf < 4; ++nf) {
                int c0 = wn + nf * 8 + qc;
                float2 xv = *reinterpret_cast<const float2*>(xr + c0);
                float2 bv = *reinterpret_cast<const float2*>(b + c0);
                c_frag[mf][nf][half * 2 + 0] = xv.x + bv.x;
                c_frag[mf][nf][half * 2 + 1] = xv.y + bv.y;
            }
        }

    // ---- Iteration 0: z1 = tanh(c) -> ping buffer ----
#pragma unroll
    for (int mf = 0; mf < 2; ++mf)
#pragma unroll
        for (int nf = 0; nf < 4; ++nf) {
            int rl = wm + mf * 16 + qr;
            int c0 = wn + nf * 8 + qc;
            __half2 h0 = __floats2half2_rn(tanh_fast(c_frag[mf][nf][0]), tanh_fast(c_frag[mf][nf][1]));
            __half2 h1 = __floats2half2_rn(tanh_fast(c_frag[mf][nf][2]), tanh_fast(c_frag[mf][nf][3]));
            *reinterpret_cast<__half2*>(smem + (Zb0 - sb) + swz(rl,     c0)) = h0;
            *reinterpret_cast<__half2*>(smem + (Zb0 - sb) + swz(rl + 8, c0)) = h1;
        }
    __syncthreads();   // W + z1 visible

    // ldmatrix per-lane address components
    const uint32_t a_r = (uint32_t)(wm + ((l >> 3) & 1) * 8 + (l & 7));
    const uint32_t a_k = (uint32_t)(((l >> 4) & 1) * 8);
    const uint32_t b_r = (uint32_t)(wn + ((l >> 4) & 1) * 8 + (l & 7));
    const uint32_t b_k = (uint32_t)(((l >> 3) & 1) * 8);

    // ---- Iterations 1..24: z <- tanh(z @ W^T + c), double-buffered ----
    for (int it = 1; it < N_ITER; ++it) {
        const uint32_t Zsrc = ((it - 1) & 1) ? Zb1 : Zb0;
        const uint32_t Zdst = ( it      & 1) ? Zb1 : Zb0;

        float acc[2][4][4];
#pragma unroll
        for (int mf = 0; mf < 2; ++mf)
#pragma unroll
            for (int nf = 0; nf < 4; ++nf)
#pragma unroll
                for (int j = 0; j < 4; ++j)
                    acc[mf][nf][j] = c_frag[mf][nf][j];

#pragma unroll
        for (int ks = 0; ks < 16; ++ks) {
            const int k0 = ks * 16;
            uint32_t a[2][4];
            ldsm4(a[0], Zsrc + swz(a_r,      k0 + a_k));
            ldsm4(a[1], Zsrc + swz(a_r + 16, k0 + a_k));
            uint32_t bf[2][4];
            ldsm4(bf[0], Wb + swz(b_r,      k0 + b_k));
            ldsm4(bf[1], Wb + swz(b_r + 16, k0 + b_k));
#pragma unroll
            for (int nf = 0; nf < 4; ++nf) {
                uint32_t bb0 = bf[nf >> 1][(nf & 1) * 2];
                uint32_t bb1 = bf[nf >> 1][(nf & 1) * 2 + 1];
                mma16816(acc[0][nf], a[0], bb0, bb1);
                mma16816(acc[1][nf], a[1], bb0, bb1);
            }
        }

        if (it == N_ITER - 1) {
            // final: accurate tanh, fp32 straight to gmem
#pragma unroll
            for (int mf = 0; mf < 2; ++mf)
#pragma unroll
                for (int nf = 0; nf < 4; ++nf) {
                    int rg = row0 + wm + mf * 16 + qr;
                    int c0 = wn + nf * 8 + qc;
                    float2 v0 = make_float2(tanh_acc(acc[mf][nf][0]), tanh_acc(acc[mf][nf][1]));
                    float2 v1 = make_float2(tanh_acc(acc[mf][nf][2]), tanh_acc(acc[mf][nf][3]));
                    *reinterpret_cast<float2*>(out + (size_t)rg * FDIM + c0)       = v0;
                    *reinterpret_cast<float2*>(out + (size_t)(rg + 8) * FDIM + c0) = v1;
                }
        } else {
#pragma unroll
            for (int mf = 0; mf < 2; ++mf)
#pragma unroll
                for (int nf = 0; nf < 4; ++nf) {
                    int rl = wm + mf * 16 + qr;
                    int c0 = wn + nf * 8 + qc;
                    __half2 h0 = __floats2half2_rn(tanh_fast(acc[mf][nf][0]), tanh_fast(acc[mf][nf][1]));
                    __half2 h1 = __floats2half2_rn(tanh_fast(acc[mf][nf][2]), tanh_fast(acc[mf][nf][3]));
                    *reinterpret_cast<__half2*>(smem + (Zdst - sb) + swz(rl,     c0)) = h0;
                    *reinterpret_cast<__half2*>(smem + (Zdst - sb) + swz(rl + 8, c0)) = h1;
                }
            __syncthreads();   // z_new visible; src buffer free next iteration
        }
    }
}

extern "C" void kernel_launch(void* const* d_in, const int* in_sizes, int n_in,
                              void* d_out, int out_size)
{
    (void)in_sizes; (void)n_in; (void)out_size;
    const float* x = (const float*)d_in[0];
    const float* W = (const float*)d_in[1];
    const float* b = (const float*)d_in[2];
    float* out = (float*)d_out;

    cudaFuncSetAttribute(fixed_point_kernel, cudaFuncAttributeMaxDynamicSharedMemorySize, SMEM_BYTES);
    fixed_point_kernel<<<32768 / TILE_M, THREADS, SMEM_BYTES>>>(x, W, b, out);
}

// round 6
// speedup vs baseline: 1.8105x; 1.8105x over previous
#include <cuda_runtime.h>
#include <cuda_fp16.h>
#include <cstdint>

#define THREADS     512
#define FDIM        256
#define N_GEMM      24          // z1 = tanh(c), then 24 GEMM iterations (25 total)
#define N_PAIRS     1024        // 32768 rows / 32 rows per tile-pair

#define ROW_BYTES   512                          // 256 halfs per row
#define W_BYTES     (FDIM * ROW_BYTES)           // 131072
#define ZT_BYTES    (16 * ROW_BYTES)             // 8192 per 16-row z buffer
#define OFF_ZA0     W_BYTES
#define OFF_ZA1     (W_BYTES + ZT_BYTES)
#define OFF_ZB0     (W_BYTES + 2 * ZT_BYTES)
#define OFF_ZB1     (W_BYTES + 3 * ZT_BYTES)
#define SMEM_BYTES  (W_BYTES + 4 * ZT_BYTES)     // 163840 (160 KB)

static __device__ __forceinline__ uint32_t smem_u32(const void* p) {
    uint32_t a;
    asm("{ .reg .u64 t; cvta.to.shared.u64 t, %1; cvt.u32.u64 %0, t; }" : "=r"(a) : "l"(p));
    return a;
}

// Byte offset of half element (r, k) in a swizzled [rows x 256] fp16 tile.
static __device__ __forceinline__ uint32_t swz(uint32_t r, uint32_t k) {
    return r * ROW_BYTES + (((k >> 3) ^ (r & 7)) << 4) + ((k & 7) << 1);
}

static __device__ __forceinline__ void ldsm4(uint32_t r[4], uint32_t addr) {
    asm volatile("ldmatrix.sync.aligned.m8n8.x4.shared.b16 {%0,%1,%2,%3}, [%4];"
                 : "=r"(r[0]), "=r"(r[1]), "=r"(r[2]), "=r"(r[3]) : "r"(addr));
}

static __device__ __forceinline__ void mma16816(float d[4], const uint32_t a[4],
                                                uint32_t b0, uint32_t b1) {
    asm volatile("mma.sync.aligned.m16n8k16.row.col.f32.f16.f16.f32 "
                 "{%0,%1,%2,%3}, {%4,%5,%6,%7}, {%8,%9}, {%0,%1,%2,%3};"
                 : "+f"(d[0]), "+f"(d[1]), "+f"(d[2]), "+f"(d[3])
                 : "r"(a[0]), "r"(a[1]), "r"(a[2]), "r"(a[3]), "r"(b0), "r"(b1));
}

static __device__ __forceinline__ float tanh_fast(float x) {
    float y;
    asm("tanh.approx.f32 %0, %1;" : "=f"(y) : "f"(x));
    return y;
}

// Accurate final-iteration tanh: 1 - 2/(1 + e^{2x}), ~1e-6 rel error.
static __device__ __forceinline__ float tanh_acc(float x) {
    float e, r;
    asm("ex2.approx.f32 %0, %1;" : "=f"(e) : "f"(x * 2.8853900817779268f));
    asm("rcp.approx.f32 %0, %1;" : "=f"(r) : "f"(1.0f + e));
    return 1.0f - 2.0f * r;
}

// One GEMM pass for a 16-row tile: acc = c + z_src @ W^T (warp's n16 slice).
// B operands come from registers; only A (z) is ldmatrix'd each k-step.
static __device__ __forceinline__ void gemm_pass(
    float acc[2][4], const float c[2][4], const uint32_t (&Breg)[64],
    uint32_t Zsrc, uint32_t a_r, uint32_t a_k)
{
#pragma unroll
    for (int nf = 0; nf < 2; ++nf)
#pragma unroll
        for (int j = 0; j < 4; ++j)
            acc[nf][j] = c[nf][j];
#pragma unroll
    for (int ks = 0; ks < 16; ++ks) {
        uint32_t a[4];
        ldsm4(a, Zsrc + swz(a_r, ks * 16 + a_k));
        mma16816(acc[0], a, Breg[ks * 4 + 0], Breg[ks * 4 + 1]);
        mma16816(acc[1], a, Breg[ks * 4 + 2], Breg[ks * 4 + 3]);
    }
}

// Store a 16-row tile's activations (fast tanh) into a z buffer.
static __device__ __forceinline__ void epi_store(
    char* smem, uint32_t zoff, const float v[2][4], int qr, int wn, int qc)
{
#pragma unroll
    for (int nf = 0; nf < 2; ++nf) {
        int c0 = wn + nf * 8 + qc;
        __half2 h0 = __floats2half2_rn(tanh_fast(v[nf][0]), tanh_fast(v[nf][1]));
        __half2 h1 = __floats2half2_rn(tanh_fast(v[nf][2]), tanh_fast(v[nf][3]));
        *reinterpret_cast<__half2*>(smem + zoff + swz(qr,     c0)) = h0;
        *reinterpret_cast<__half2*>(smem + zoff + swz(qr + 8, c0)) = h1;
    }
}

__global__ void __launch_bounds__(THREADS, 1)
fixed_point_kernel(const float* __restrict__ x, const float* __restrict__ W,
                   const float* __restrict__ b, float* __restrict__ out)
{
    extern __shared__ char smem[];
    const uint32_t sb = smem_u32(smem);
    const uint32_t Wb = sb;

    const int tid = threadIdx.x;
    const int wid = tid >> 5;
    const int l   = tid & 31;
    const int wn  = wid << 4;                 // this warp's 16-col slice of N=256
    const int qr  = l >> 2;
    const int qc  = (l & 3) << 1;

    // ---- One-time: W -> SMEM fp16 swizzled [n][k] ----
    for (int idx = tid; idx < FDIM * (FDIM / 4); idx += THREADS) {
        int n  = idx >> 6;
        int k4 = (idx & 63) << 2;
        float4 wv = *reinterpret_cast<const float4*>(W + n * FDIM + k4);
        __half2 h0 = __floats2half2_rn(wv.x, wv.y);
        __half2 h1 = __floats2half2_rn(wv.z, wv.w);
        uint2 v;
        v.x = *reinterpret_cast<uint32_t*>(&h0);
        v.y = *reinterpret_cast<uint32_t*>(&h1);
        *reinterpret_cast<uint2*>(smem + swz(n, k4)) = v;
    }
    __syncthreads();

    // ---- One-time: B fragments (whole K for this warp's n16 slice) -> registers ----
    const uint32_t b_r = (uint32_t)(wn + ((l >> 4) & 1) * 8 + (l & 7));
    const uint32_t b_k = (uint32_t)(((l >> 3) & 1) * 8);
    uint32_t Breg[64];
#pragma unroll
    for (int ks = 0; ks < 16; ++ks)
        ldsm4(&Breg[ks * 4], Wb + swz(b_r, ks * 16 + b_k));

    // ---- One-time: bias values for this thread's output columns ----
    float bias[2][2];
#pragma unroll
    for (int nf = 0; nf < 2; ++nf) {
        float2 bv = *reinterpret_cast<const float2*>(b + wn + nf * 8 + qc);
        bias[nf][0] = bv.x;
        bias[nf][1] = bv.y;
    }

    const uint32_t a_r = (uint32_t)(((l >> 3) & 1) * 8 + (l & 7));
    const uint32_t a_k = (uint32_t)(((l >> 4) & 1) * 8);
    const uint32_t ZA0 = sb + OFF_ZA0, ZA1 = sb + OFF_ZA1;
    const uint32_t ZB0 = sb + OFF_ZB0, ZB1 = sb + OFF_ZB1;

    // ---- Persistent loop over 32-row tile pairs ----
    for (int pair = blockIdx.x; pair < N_PAIRS; pair += gridDim.x) {
        const int row0 = pair * 32;           // tile A rows [row0, row0+16), B next 16

        // c = x + b fragments for both 16-row tiles
        float cA[2][4], cB[2][4];
#pragma unroll
        for (int half = 0; half < 2; ++half) {
            int rA = row0 + qr + half * 8;
            const float* xrA = x + (size_t)rA * FDIM;
            const float* xrB = xrA + 16 * FDIM;
#pragma unroll
            for (int nf = 0; nf < 2; ++nf) {
                int c0 = wn + nf * 8 + qc;
                float2 xa = *reinterpret_cast<const float2*>(xrA + c0);
                float2 xb = *reinterpret_cast<const float2*>(xrB + c0);
                cA[nf][half * 2 + 0] = xa.x + bias[nf][0];
                cA[nf][half * 2 + 1] = xa.y + bias[nf][1];
                cB[nf][half * 2 + 0] = xb.x + bias[nf][0];
                cB[nf][half * 2 + 1] = xb.y + bias[nf][1];
            }
        }

        // Iteration 0: z1 = tanh(c) -> ping buffers
        epi_store(smem, OFF_ZA0, cA, qr, wn, qc);
        epi_store(smem, OFF_ZB0, cB, qr, wn, qc);
        __syncthreads();

        // Iterations 1..23 (ping-pong z buffers, ONE barrier per iteration)
        float acc[2][4];
#pragma unroll 1
        for (int it = 1; it < N_GEMM; ++it) {
            const bool odd = (it & 1) != 0;
            const uint32_t ZAsrc = odd ? ZA0 : ZA1;
            const uint32_t ZBsrc = odd ? ZB0 : ZB1;
            const uint32_t zAdst = odd ? OFF_ZA1 : OFF_ZA0;
            const uint32_t zBdst = odd ? OFF_ZB1 : OFF_ZB0;

            gemm_pass(acc, cA, Breg, ZAsrc, a_r, a_k);
            epi_store(smem, zAdst, acc, qr, wn, qc);
            gemm_pass(acc, cB, Breg, ZBsrc, a_r, a_k);
            epi_store(smem, zBdst, acc, qr, wn, qc);
            __syncthreads();
        }

        // Final iteration (it = 24, sources are pong buffers): accurate tanh -> gmem
        gemm_pass(acc, cA, Breg, ZA1, a_r, a_k);
#pragma unroll
        for (int nf = 0; nf < 2; ++nf) {
            int rg = row0 + qr;
            int c0 = wn + nf * 8 + qc;
            float2 v0 = make_float2(tanh_acc(acc[nf][0]), tanh_acc(acc[nf][1]));
            float2 v1 = make_float2(tanh_acc(acc[nf][2]), tanh_acc(acc[nf][3]));
            *reinterpret_cast<float2*>(out + (size_t)rg * FDIM + c0)       = v0;
            *reinterpret_cast<float2*>(out + (size_t)(rg + 8) * FDIM + c0) = v1;
        }
        gemm_pass(acc, cB, Breg, ZB1, a_r, a_k);
#pragma unroll
        for (int nf = 0; nf < 2; ++nf) {
            int rg = row0 + 16 + qr;
            int c0 = wn + nf * 8 + qc;
            float2 v0 = make_float2(tanh_acc(acc[nf][0]), tanh_acc(acc[nf][1]));
            float2 v1 = make_float2(tanh_acc(acc[nf][2]), tanh_acc(acc[nf][3]));
            *reinterpret_cast<float2*>(out + (size_t)rg * FDIM + c0)       = v0;
            *reinterpret_cast<float2*>(out + (size_t)(rg + 8) * FDIM + c0) = v1;
        }
        __syncthreads();   // z buffers safe to overwrite by next pair's iteration 0
    }
}

extern "C" void kernel_launch(void* const* d_in, const int* in_sizes, int n_in,
                              void* d_out, int out_size)
{
    (void)in_sizes; (void)n_in; (void)out_size;
    const float* x = (const float*)d_in[0];
    const float* W = (const float*)d_in[1];
    const float* b = (const float*)d_in[2];
    float* out = (float*)d_out;

    int dev = 0, sms = 0;
    cudaGetDevice(&dev);
    cudaDeviceGetAttribute(&sms, cudaDevAttrMultiProcessorCount, dev);
    int grid = sms > 0 ? sms : 128;
    if (grid > N_PAIRS) grid = N_PAIRS;

    cudaFuncSetAttribute(fixed_point_kernel, cudaFuncAttributeMaxDynamicSharedMemorySize, SMEM_BYTES);
    fixed_point_kernel<<<grid, THREADS, SMEM_BYTES>>>(x, W, b, out);
}